// round 8
// baseline (speedup 1.0000x reference)
#include <cuda_runtime.h>

#define TT 512
#define BB 64
#define II 512
#define HH 512

// smem layout constants (element strides)
#define WSS 34     // float2 stride per k2 row of weights (32 used)
#define HSS 260    // float2 stride per batch row of h (256 used; 16B-aligned rows)
#define RPS 146    // ull stride per outpos in reduction array
#define WS_BYTES (256 * WSS * 8)            // 69632
#define HS_BYTES (16 * HSS * 8)             // 33280
#define RED_OFF  (WS_BYTES + HS_BYTES)      // 102912 (16B aligned)
#define SMEM_TOTAL (RED_OFF + 32 * RPS * 8) // 140288

// Static device scratch (no allocations allowed)
__device__ float g_xp[2][TT][BB][HH];    // input projections per direction
__device__ float g_h[2][2][BB][HH];      // [dir][buf][b][h] double-buffered state
__device__ unsigned g_flag[2][64][32];   // per-CTA barrier flags, 128B padded (monotonic)

typedef unsigned long long ull;

__device__ __forceinline__ void fma2(ull& acc, ull a, ull b) {
    asm("fma.rn.f32x2 %0, %1, %2, %0;" : "+l"(acc) : "l"(a), "l"(b));
}
__device__ __forceinline__ ull add2(ull a, ull b) {
    ull r; asm("add.rn.f32x2 %0, %1, %2;" : "=l"(r) : "l"(a), "l"(b)); return r;
}
__device__ __forceinline__ float2 unpack2(ull v) {
    float2 r; asm("mov.b64 {%0, %1}, %2;" : "=f"(r.x), "=f"(r.y) : "l"(v)); return r;
}
__device__ __forceinline__ unsigned ld_acq(const unsigned* p) {
    unsigned v; asm volatile("ld.acquire.gpu.u32 %0, [%1];" : "=r"(v) : "l"(p) : "memory");
    return v;
}
__device__ __forceinline__ void st_rel(unsigned* p, unsigned v) {
    asm volatile("st.release.gpu.u32 [%0], %1;" :: "l"(p), "r"(v) : "memory");
}

// ---------------------------------------------------------------------------
// Phase 1: xp[dir][t][b][n] = sum_i x[b][t][i] * W[n][i] + bias[n]
// ---------------------------------------------------------------------------
__global__ __launch_bounds__(256) void xproj_kernel(
    const float* __restrict__ x,
    const float* __restrict__ Wf, const float* __restrict__ bf,
    const float* __restrict__ Wb, const float* __restrict__ bbias) {
    const int dir = blockIdx.z;
    const float* __restrict__ W    = dir ? Wb : Wf;
    const float* __restrict__ bias = dir ? bbias : bf;
    const int t = blockIdx.y;
    const int n_base = blockIdx.x * 64;

    __shared__ float2 a2[8][66];   // [k2][m]
    __shared__ float2 b2[8][66];   // [k2][n]

    const int tid = threadIdx.x;
    const int w = tid >> 5, lane = tid & 31;
    const int mgrp = ((w >> 1) << 2) | (lane >> 3);  // 0..15
    const int ngrp = ((w & 1) << 3) | (lane & 7);    // 0..15
    const int m0 = mgrp << 2, n0l = ngrp << 2;

    const int lr = tid >> 2;
    const int lq = (tid & 3) << 2;
    const float* arow = x + ((size_t)lr * TT + t) * II + lq;
    const float* brow = W + (size_t)(n_base + lr) * II + lq;

    ull acc[4][4];
#pragma unroll
    for (int i = 0; i < 4; i++)
#pragma unroll
        for (int j = 0; j < 4; j++) acc[i][j] = 0ull;

    for (int st = 0; st < 32; st++) {
        float4 pa = *(const float4*)(arow + st * 16);
        float4 pb = *(const float4*)(brow + st * 16);
        __syncthreads();
        a2[(lq >> 1) + 0][lr] = make_float2(pa.x, pa.y);
        a2[(lq >> 1) + 1][lr] = make_float2(pa.z, pa.w);
        b2[(lq >> 1) + 0][lr] = make_float2(pb.x, pb.y);
        b2[(lq >> 1) + 1][lr] = make_float2(pb.z, pb.w);
        __syncthreads();
#pragma unroll
        for (int k2 = 0; k2 < 8; k2++) {
            ulonglong2 av0 = *(const ulonglong2*)&a2[k2][m0];
            ulonglong2 av1 = *(const ulonglong2*)&a2[k2][m0 + 2];
            ulonglong2 bv0 = *(const ulonglong2*)&b2[k2][n0l];
            ulonglong2 bv1 = *(const ulonglong2*)&b2[k2][n0l + 2];
            ull am[4] = {av0.x, av0.y, av1.x, av1.y};
            ull bn[4] = {bv0.x, bv0.y, bv1.x, bv1.y};
#pragma unroll
            for (int i = 0; i < 4; i++)
#pragma unroll
                for (int j = 0; j < 4; j++)
                    fma2(acc[i][j], am[i], bn[j]);
        }
    }

    float4 bv = *(const float4*)(bias + n_base + n0l);
#pragma unroll
    for (int i = 0; i < 4; i++) {
        float2 s0 = unpack2(acc[i][0]);
        float2 s1 = unpack2(acc[i][1]);
        float2 s2 = unpack2(acc[i][2]);
        float2 s3 = unpack2(acc[i][3]);
        float4 v;
        v.x = s0.x + s0.y + bv.x;
        v.y = s1.x + s1.y + bv.y;
        v.z = s2.x + s2.y + bv.z;
        v.w = s3.x + s3.y + bv.w;
        *(float4*)&g_xp[dir][t][m0 + i][n_base + n0l] = v;
    }
}

// ---------------------------------------------------------------------------
// Phase 2: persistent recurrence. 128 CTAs (64/dir), 256 threads, 1 CTA/SM.
// CTA tile 16b x 32n; thread tile 4b x 4n; k-split 8 (one k-slice per warp).
// h loads are float4 (2 k-pairs per LDS.128). b-group-local flag barrier.
// ---------------------------------------------------------------------------
__global__ __launch_bounds__(256, 1) void rnn_persist(
    const float* __restrict__ Whf, const float* __restrict__ Whb,
    const float* __restrict__ h0f, const float* __restrict__ h0b,
    float* __restrict__ out) {
    extern __shared__ char smem[];
    float2* ws = (float2*)smem;                 // [256][WSS]
    float2* hs = (float2*)(smem + WS_BYTES);    // [16][HSS]
    ull* red   = (ull*)(smem + RED_OFF);        // [32 outpos][RPS]

    const int cta = blockIdx.x;
    const int dir = cta & 1;
    const int slice = cta >> 1;             // 0..63
    const int grp = slice >> 4;             // b-group 0..3
    const int b_base = grp * 16;
    const int n_base = (slice & 15) * 32;
    const float* __restrict__ Wh = dir ? Whb : Whf;
    const float* __restrict__ h0 = dir ? h0b : h0f;
    const int tid = threadIdx.x;
    const int ks = tid >> 5;                // warp id = k-slice (k2 in [32ks,32ks+32))
    const int lane = tid & 31;
    const int ngrp = lane >> 2;             // 0..7  (4 n each)
    const int bgrp = lane & 3;              // 0..3  (4 b each)

    // one-time weight fill: ws[k2][nl] = {W[n][2k2], W[n][2k2+1]}
    for (int idx = tid; idx < 32 * 256; idx += 256) {
        int nl = idx >> 8, k2 = idx & 255;
        ws[k2 * WSS + nl] =
            *(const float2*)(Wh + (size_t)(n_base + nl) * HH + 2 * k2);
    }

    // reducer assignment: 2 outputs (adjacent n) per thread
    const int ro = tid >> 3, j = tid & 7;   // outpos, pair index
    const int i0 = 2 * j;
    const int rb = b_base + (ro & 3) * 4 + (i0 >> 2);
    const int rn = n_base + (ro >> 2) * 4 + (i0 & 3);

    const int sbr = tid >> 4;    // staging batch row 0..15
    const int sc = tid & 15;     // staging chunk base

    const float2* wp = ws + (size_t)(ks * 32) * WSS + 4 * ngrp;
    const ulonglong2* hrow =
        (const ulonglong2*)hs + (size_t)(4 * bgrp) * (HSS / 2) + 16 * ks;

    // replay-monotonic barrier base (only this CTA writes its flag)
    const unsigned base = ld_acq(&g_flag[dir][slice][0]);
    __syncthreads();

    for (int s = 0; s < TT; s++) {
        const int t = dir ? (TT - 1 - s) : s;
        const float* __restrict__ hin =
            (s == 0) ? h0 : (const float*)g_h[dir][s & 1];
        float* __restrict__ hout = (float*)g_h[dir][(s & 1) ^ 1];

        // stage h slice (16 x 512) into hs[b][k2], STS.128
#pragma unroll
        for (int i = 0; i < 8; i++) {
            int c = sc + 16 * i;   // float4 chunk 0..127
            float4 v = *(const float4*)(hin + (size_t)(b_base + sbr) * HH + 4 * c);
            *(float4*)&hs[sbr * HSS + 2 * c] = v;
        }
        float2 xpv = *(const float2*)&g_xp[dir][t][rb][rn];
        __syncthreads();

        // mainloop: 4b x 4n per thread, 2 k2 per iteration (float4 h loads)
        ull acc[16];
#pragma unroll
        for (int i = 0; i < 16; i++) acc[i] = 0ull;
#pragma unroll 4
        for (int kk2 = 0; kk2 < 16; kk2++) {
            const float2* wr = wp + (size_t)(2 * kk2) * WSS;
            ulonglong2 wa0 = *(const ulonglong2*)(wr);
            ulonglong2 wa1 = *(const ulonglong2*)(wr + 2);
            ulonglong2 wb0 = *(const ulonglong2*)(wr + WSS);
            ulonglong2 wb1 = *(const ulonglong2*)(wr + WSS + 2);
            ulonglong2 h0v = hrow[kk2];
            ulonglong2 h1v = hrow[(HSS / 2) + kk2];
            ulonglong2 h2v = hrow[2 * (HSS / 2) + kk2];
            ulonglong2 h3v = hrow[3 * (HSS / 2) + kk2];
            fma2(acc[0],  h0v.x, wa0.x); fma2(acc[1],  h0v.x, wa0.y);
            fma2(acc[2],  h0v.x, wa1.x); fma2(acc[3],  h0v.x, wa1.y);
            fma2(acc[0],  h0v.y, wb0.x); fma2(acc[1],  h0v.y, wb0.y);
            fma2(acc[2],  h0v.y, wb1.x); fma2(acc[3],  h0v.y, wb1.y);
            fma2(acc[4],  h1v.x, wa0.x); fma2(acc[5],  h1v.x, wa0.y);
            fma2(acc[6],  h1v.x, wa1.x); fma2(acc[7],  h1v.x, wa1.y);
            fma2(acc[4],  h1v.y, wb0.x); fma2(acc[5],  h1v.y, wb0.y);
            fma2(acc[6],  h1v.y, wb1.x); fma2(acc[7],  h1v.y, wb1.y);
            fma2(acc[8],  h2v.x, wa0.x); fma2(acc[9],  h2v.x, wa0.y);
            fma2(acc[10], h2v.x, wa1.x); fma2(acc[11], h2v.x, wa1.y);
            fma2(acc[8],  h2v.y, wb0.x); fma2(acc[9],  h2v.y, wb0.y);
            fma2(acc[10], h2v.y, wb1.x); fma2(acc[11], h2v.y, wb1.y);
            fma2(acc[12], h3v.x, wa0.x); fma2(acc[13], h3v.x, wa0.y);
            fma2(acc[14], h3v.x, wa1.x); fma2(acc[15], h3v.x, wa1.y);
            fma2(acc[12], h3v.y, wb0.x); fma2(acc[13], h3v.y, wb0.y);
            fma2(acc[14], h3v.y, wb1.x); fma2(acc[15], h3v.y, wb1.y);
        }

        // write partials: red[outpos(=lane)][i][ks]
#pragma unroll
        for (int i = 0; i < 16; i++)
            red[lane * RPS + i * 9 + ks] = acc[i];
        __syncthreads();

        // 8-way reduction: this thread's 2 outputs are i0, i0+1 at outpos ro
        const ulonglong2* q = (const ulonglong2*)(red + ro * RPS + 18 * j);
        ulonglong2 q0 = q[0], q1 = q[1], q2 = q[2], q3 = q[3];
        ulonglong2 q4 = q[4], q5 = q[5], q6 = q[6], q7 = q[7], q8 = q[8];
        ull s0 = add2(add2(add2(q0.x, q0.y), add2(q1.x, q1.y)),
                      add2(add2(q2.x, q2.y), add2(q3.x, q3.y)));
        ull s1 = add2(add2(add2(q4.y, q5.x), add2(q5.y, q6.x)),
                      add2(add2(q6.y, q7.x), add2(q7.y, q8.x)));
        float2 f0 = unpack2(s0);
        float2 f1 = unpack2(s1);
        float v0 = tanhf(f0.x + f0.y + xpv.x);
        float v1 = tanhf(f1.x + f1.y + xpv.y);

        if (s < TT - 1) {
            *(float2*)(hout + (size_t)rb * HH + rn) = make_float2(v0, v1);
            __syncthreads();                 // all hout writes issued
            if (tid == 0) st_rel(&g_flag[dir][slice][0], base + s + 1);
            // y store off the critical path
            *(float2*)(out + ((size_t)rb * TT + t) * (2 * HH) +
                       (size_t)dir * HH + rn) = make_float2(v0, v1);
            // b-group-local poll (16 CTAs)
            if (tid < 16) {
                const unsigned tgt = base + (unsigned)(s + 1);
                const unsigned* f = &g_flag[dir][grp * 16 + tid][0];
                while (ld_acq(f) < tgt) {}
            }
            __syncthreads();
        } else {
            *(float2*)(out + ((size_t)rb * TT + t) * (2 * HH) +
                       (size_t)dir * HH + rn) = make_float2(v0, v1);
            float* hT = out + (size_t)BB * TT * 2 * HH + (size_t)dir * BB * HH;
            *(float2*)(hT + (size_t)rb * HH + rn) = make_float2(v0, v1);
        }
    }
}

extern "C" void kernel_launch(void* const* d_in, const int* in_sizes, int n_in,
                              void* d_out, int out_size) {
    const float* x     = (const float*)d_in[0];
    const float* h0f   = (const float*)d_in[1];
    const float* h0b   = (const float*)d_in[2];
    const float* Wxf_w = (const float*)d_in[3];
    const float* Wxf_b = (const float*)d_in[4];
    const float* Whf_w = (const float*)d_in[5];
    const float* Wxb_w = (const float*)d_in[6];
    const float* Wxb_b = (const float*)d_in[7];
    const float* Whb_w = (const float*)d_in[8];
    float* out = (float*)d_out;

    static int smem_set = 0;
    if (!smem_set) {
        cudaFuncSetAttribute(rnn_persist,
                             cudaFuncAttributeMaxDynamicSharedMemorySize,
                             SMEM_TOTAL);
        smem_set = 1;
    }

    xproj_kernel<<<dim3(HH / 64, TT, 2), 256>>>(x, Wxf_w, Wxf_b, Wxb_w, Wxb_b);
    rnn_persist<<<128, 256, SMEM_TOTAL>>>(Whf_w, Whb_w, h0f, h0b, out);
}

// round 9
// speedup vs baseline: 1.4411x; 1.4411x over previous
#include <cuda_runtime.h>

#define TT 512
#define BB 64
#define II 512
#define HH 512

// smem layout constants (element strides)
#define WSS 34     // float2 stride per k2 row of weights (32 used)
#define HSS 259    // float2 stride per batch row of h (256 used; odd => bank rotation)
#define RPS 146    // ull stride per outpos in reduction array (>= 8*18=144)
#define WS_BYTES (256 * WSS * 8)            // 69632
#define HS_BYTES (16 * HSS * 8)             // 33152
#define RED_OFF  (WS_BYTES + HS_BYTES)      // 102784 (16B aligned)
#define SMEM_TOTAL (RED_OFF + 32 * RPS * 8) // 140160

// Static device scratch (no allocations allowed)
__device__ float g_xp[2][TT][BB][HH];    // input projections per direction
__device__ float g_h[2][2][BB][HH];      // [dir][buf][b][h] double-buffered state
__device__ unsigned g_flag[2][64][32];   // per-CTA barrier flags, 128B padded (monotonic)

typedef unsigned long long ull;

__device__ __forceinline__ void fma2(ull& acc, ull a, ull b) {
    asm("fma.rn.f32x2 %0, %1, %2, %0;" : "+l"(acc) : "l"(a), "l"(b));
}
__device__ __forceinline__ ull add2(ull a, ull b) {
    ull r; asm("add.rn.f32x2 %0, %1, %2;" : "=l"(r) : "l"(a), "l"(b)); return r;
}
__device__ __forceinline__ float2 unpack2(ull v) {
    float2 r; asm("mov.b64 {%0, %1}, %2;" : "=f"(r.x), "=f"(r.y) : "l"(v)); return r;
}
__device__ __forceinline__ unsigned ld_acq(const unsigned* p) {
    unsigned v; asm volatile("ld.acquire.gpu.u32 %0, [%1];" : "=r"(v) : "l"(p) : "memory");
    return v;
}
__device__ __forceinline__ void st_rel(unsigned* p, unsigned v) {
    asm volatile("st.release.gpu.u32 [%0], %1;" :: "l"(p), "r"(v) : "memory");
}

// ---------------------------------------------------------------------------
// Phase 1: xp[dir][t][b][n] = sum_i x[b][t][i] * W[n][i] + bias[n]
// ---------------------------------------------------------------------------
__global__ __launch_bounds__(256) void xproj_kernel(
    const float* __restrict__ x,
    const float* __restrict__ Wf, const float* __restrict__ bf,
    const float* __restrict__ Wb, const float* __restrict__ bbias) {
    const int dir = blockIdx.z;
    const float* __restrict__ W    = dir ? Wb : Wf;
    const float* __restrict__ bias = dir ? bbias : bf;
    const int t = blockIdx.y;
    const int n_base = blockIdx.x * 64;

    __shared__ float2 a2[8][66];   // [k2][m]
    __shared__ float2 b2[8][66];   // [k2][n]

    const int tid = threadIdx.x;
    const int w = tid >> 5, lane = tid & 31;
    const int mgrp = ((w >> 1) << 2) | (lane >> 3);  // 0..15
    const int ngrp = ((w & 1) << 3) | (lane & 7);    // 0..15
    const int m0 = mgrp << 2, n0l = ngrp << 2;

    const int lr = tid >> 2;
    const int lq = (tid & 3) << 2;
    const float* arow = x + ((size_t)lr * TT + t) * II + lq;
    const float* brow = W + (size_t)(n_base + lr) * II + lq;

    ull acc[4][4];
#pragma unroll
    for (int i = 0; i < 4; i++)
#pragma unroll
        for (int j = 0; j < 4; j++) acc[i][j] = 0ull;

    for (int st = 0; st < 32; st++) {
        float4 pa = *(const float4*)(arow + st * 16);
        float4 pb = *(const float4*)(brow + st * 16);
        __syncthreads();
        a2[(lq >> 1) + 0][lr] = make_float2(pa.x, pa.y);
        a2[(lq >> 1) + 1][lr] = make_float2(pa.z, pa.w);
        b2[(lq >> 1) + 0][lr] = make_float2(pb.x, pb.y);
        b2[(lq >> 1) + 1][lr] = make_float2(pb.z, pb.w);
        __syncthreads();
#pragma unroll
        for (int k2 = 0; k2 < 8; k2++) {
            ulonglong2 av0 = *(const ulonglong2*)&a2[k2][m0];
            ulonglong2 av1 = *(const ulonglong2*)&a2[k2][m0 + 2];
            ulonglong2 bv0 = *(const ulonglong2*)&b2[k2][n0l];
            ulonglong2 bv1 = *(const ulonglong2*)&b2[k2][n0l + 2];
            ull am[4] = {av0.x, av0.y, av1.x, av1.y};
            ull bn[4] = {bv0.x, bv0.y, bv1.x, bv1.y};
#pragma unroll
            for (int i = 0; i < 4; i++)
#pragma unroll
                for (int j = 0; j < 4; j++)
                    fma2(acc[i][j], am[i], bn[j]);
        }
    }

    float4 bv = *(const float4*)(bias + n_base + n0l);
#pragma unroll
    for (int i = 0; i < 4; i++) {
        float2 s0 = unpack2(acc[i][0]);
        float2 s1 = unpack2(acc[i][1]);
        float2 s2 = unpack2(acc[i][2]);
        float2 s3 = unpack2(acc[i][3]);
        float4 v;
        v.x = s0.x + s0.y + bv.x;
        v.y = s1.x + s1.y + bv.y;
        v.z = s2.x + s2.y + bv.z;
        v.w = s3.x + s3.y + bv.w;
        *(float4*)&g_xp[dir][t][m0 + i][n_base + n0l] = v;
    }
}

// ---------------------------------------------------------------------------
// Phase 2: persistent recurrence. 128 CTAs (64/dir), 256 threads, 1 CTA/SM.
// CTA tile 16b x 32n; thread tile 4b x 4n; k-split 8 (one k-slice per warp).
// R6 mainloop (conflict-free LDS.64 h, HSS=259) + b-group-local flag barrier
// + y stores after flag release + STS.128 reduction writes.
// ---------------------------------------------------------------------------
__global__ __launch_bounds__(256, 1) void rnn_persist(
    const float* __restrict__ Whf, const float* __restrict__ Whb,
    const float* __restrict__ h0f, const float* __restrict__ h0b,
    float* __restrict__ out) {
    extern __shared__ char smem[];
    float2* ws = (float2*)smem;                 // [256][WSS]
    float2* hs = (float2*)(smem + WS_BYTES);    // [16][HSS]
    ull* red   = (ull*)(smem + RED_OFF);        // [32 outpos][8 ks][18]

    const int cta = blockIdx.x;
    const int dir = cta & 1;
    const int slice = cta >> 1;             // 0..63
    const int grp = slice >> 4;             // b-group 0..3
    const int b_base = grp * 16;
    const int n_base = (slice & 15) * 32;
    const float* __restrict__ Wh = dir ? Whb : Whf;
    const float* __restrict__ h0 = dir ? h0b : h0f;
    const int tid = threadIdx.x;
    const int ks = tid >> 5;                // warp id = k-slice (k2 in [32ks,32ks+32))
    const int lane = tid & 31;
    const int ngrp = lane >> 2;             // 0..7  (4 n each)
    const int bgrp = lane & 3;              // 0..3  (4 b each)

    // one-time weight fill: ws[k2][nl] = {W[n][2k2], W[n][2k2+1]}
    for (int idx = tid; idx < 32 * 256; idx += 256) {
        int nl = idx >> 8, k2 = idx & 255;
        ws[k2 * WSS + nl] =
            *(const float2*)(Wh + (size_t)(n_base + nl) * HH + 2 * k2);
    }

    // reducer assignment: 2 outputs (adjacent n) per thread
    const int ro = tid >> 3, j = tid & 7;   // outpos, pair index
    const int i0 = 2 * j;
    const int rb = b_base + (ro & 3) * 4 + (i0 >> 2);
    const int rn = n_base + (ro >> 2) * 4 + (i0 & 3);

    const int sbr = tid >> 4;    // staging batch row 0..15
    const int sc = tid & 15;     // staging chunk base

    const float2* wp = ws + (size_t)(ks * 32) * WSS + 4 * ngrp;
    const float2* hp = hs + (size_t)(4 * bgrp) * HSS + ks * 32;

    // replay-monotonic barrier base (only this CTA writes its flag)
    const unsigned base = ld_acq(&g_flag[dir][slice][0]);
    __syncthreads();

    for (int s = 0; s < TT; s++) {
        const int t = dir ? (TT - 1 - s) : s;
        const float* __restrict__ hin =
            (s == 0) ? h0 : (const float*)g_h[dir][s & 1];
        float* __restrict__ hout = (float*)g_h[dir][(s & 1) ^ 1];

        // stage h slice (16 x 512) into hs[b][k2] (float2 per k2)
#pragma unroll
        for (int i = 0; i < 8; i++) {
            int c = sc + 16 * i;   // float4 chunk 0..127
            float4 v = *(const float4*)(hin + (size_t)(b_base + sbr) * HH + 4 * c);
            hs[sbr * HSS + 2 * c]     = make_float2(v.x, v.y);
            hs[sbr * HSS + 2 * c + 1] = make_float2(v.z, v.w);
        }
        float2 xpv = *(const float2*)&g_xp[dir][t][rb][rn];
        __syncthreads();

        // mainloop: 4b x 4n per thread over this warp's 32 k2
        ull acc[16];
#pragma unroll
        for (int i = 0; i < 16; i++) acc[i] = 0ull;
#pragma unroll 8
        for (int kk = 0; kk < 32; kk++) {
            ull hv0 = *(const ull*)(hp + kk);
            ull hv1 = *(const ull*)(hp + kk + HSS);
            ull hv2 = *(const ull*)(hp + kk + 2 * HSS);
            ull hv3 = *(const ull*)(hp + kk + 3 * HSS);
            ulonglong2 w01 = *(const ulonglong2*)(wp + (size_t)kk * WSS);
            ulonglong2 w23 = *(const ulonglong2*)(wp + (size_t)kk * WSS + 2);
            fma2(acc[0],  hv0, w01.x); fma2(acc[1],  hv0, w01.y);
            fma2(acc[2],  hv0, w23.x); fma2(acc[3],  hv0, w23.y);
            fma2(acc[4],  hv1, w01.x); fma2(acc[5],  hv1, w01.y);
            fma2(acc[6],  hv1, w23.x); fma2(acc[7],  hv1, w23.y);
            fma2(acc[8],  hv2, w01.x); fma2(acc[9],  hv2, w01.y);
            fma2(acc[10], hv2, w23.x); fma2(acc[11], hv2, w23.y);
            fma2(acc[12], hv3, w01.x); fma2(acc[13], hv3, w01.y);
            fma2(acc[14], hv3, w23.x); fma2(acc[15], hv3, w23.y);
        }

        // write partials: red[outpos(=lane)][ks][i], 8 STS.128
#pragma unroll
        for (int m = 0; m < 8; m++)
            *(ulonglong2*)(red + lane * RPS + ks * 18 + 2 * m) =
                make_ulonglong2(acc[2 * m], acc[2 * m + 1]);
        __syncthreads();

        // 8-way reduction: outputs i0, i0+1 at outpos ro
        ull s0 = 0ull, s1 = 0ull;
#pragma unroll
        for (int k = 0; k < 8; k++) {
            ulonglong2 q = *(const ulonglong2*)(red + ro * RPS + k * 18 + i0);
            s0 = add2(s0, q.x);
            s1 = add2(s1, q.y);
        }
        float2 f0 = unpack2(s0);
        float2 f1 = unpack2(s1);
        float v0 = tanhf(f0.x + f0.y + xpv.x);
        float v1 = tanhf(f1.x + f1.y + xpv.y);

        if (s < TT - 1) {
            *(float2*)(hout + (size_t)rb * HH + rn) = make_float2(v0, v1);
            __syncthreads();                 // all hout writes issued
            if (tid == 0) st_rel(&g_flag[dir][slice][0], base + s + 1);
            // y store off the inter-CTA critical path
            *(float2*)(out + ((size_t)rb * TT + t) * (2 * HH) +
                       (size_t)dir * HH + rn) = make_float2(v0, v1);
            // b-group-local poll (16 CTAs share this b_base)
            if (tid < 16) {
                const unsigned tgt = base + (unsigned)(s + 1);
                const unsigned* f = &g_flag[dir][grp * 16 + tid][0];
                while (ld_acq(f) < tgt) {}
            }
            __syncthreads();
        } else {
            *(float2*)(out + ((size_t)rb * TT + t) * (2 * HH) +
                       (size_t)dir * HH + rn) = make_float2(v0, v1);
            float* hT = out + (size_t)BB * TT * 2 * HH + (size_t)dir * BB * HH;
            *(float2*)(hT + (size_t)rb * HH + rn) = make_float2(v0, v1);
        }
    }
}

extern "C" void kernel_launch(void* const* d_in, const int* in_sizes, int n_in,
                              void* d_out, int out_size) {
    const float* x     = (const float*)d_in[0];
    const float* h0f   = (const float*)d_in[1];
    const float* h0b   = (const float*)d_in[2];
    const float* Wxf_w = (const float*)d_in[3];
    const float* Wxf_b = (const float*)d_in[4];
    const float* Whf_w = (const float*)d_in[5];
    const float* Wxb_w = (const float*)d_in[6];
    const float* Wxb_b = (const float*)d_in[7];
    const float* Whb_w = (const float*)d_in[8];
    float* out = (float*)d_out;

    static int smem_set = 0;
    if (!smem_set) {
        cudaFuncSetAttribute(rnn_persist,
                             cudaFuncAttributeMaxDynamicSharedMemorySize,
                             SMEM_TOTAL);
        smem_set = 1;
    }

    xproj_kernel<<<dim3(HH / 64, TT, 2), 256>>>(x, Wxf_w, Wxf_b, Wxb_w, Wxb_b);
    rnn_persist<<<128, 256, SMEM_TOTAL>>>(Whf_w, Whb_w, h0f, h0b, out);
}